// round 10
// baseline (speedup 1.0000x reference)
#include <cuda_runtime.h>
#include <cuda_bf16.h>
#include <cstdint>

// Shapes: x (4,2048,2048) -> M=8192, K=2048; weight (8192,2048) -> N=8192.
#define M_TOK 8192
#define K_DIM 2048
#define N_OUT 8192
#define W_ELEMS (N_OUT * K_DIM)
#define X_ELEMS (M_TOK * K_DIM)

// GEMM tiling (bf16: BK=64 elems = 128 bytes per SMEM row)
#define BM 128
#define BN 128
#define BK 64
#define CHUNKS (K_DIM / BK)          // 32
#define STAGES 3
#define A_BYTES (BM * 128)           // 16384
#define B_BYTES (BN * 128)           // 16384
#define STAGE_BYTES (A_BYTES + B_BYTES)   // 32768
#define SMEM_TOTAL (1024 + STAGES * STAGE_BYTES)   // 99328 -> 2 CTAs/SM

// ---- device scratch ----
__device__ float g_gamma;
__device__ float g_partial[2048];
__device__ float g_scale[M_TOK];
__device__ __nv_bfloat16 g_xb[X_ELEMS];
__device__ __nv_bfloat16 g_wb[W_ELEMS];

// ======================= helpers =======================
__device__ __forceinline__ uint32_t smem_u32(const void* p) {
    uint32_t a;
    asm("{ .reg .u64 t; cvta.to.shared.u64 t, %1; cvt.u32.u64 %0, t; }" : "=r"(a) : "l"(p));
    return a;
}
#define SW128(o) ((o) ^ (((o) >> 3) & 0x70))

__device__ __forceinline__ void cp16(uint32_t dst, const void* src) {
    asm volatile("cp.async.cg.shared.global [%0], [%1], 16;" :: "r"(dst), "l"(src));
}
#define CP_COMMIT() asm volatile("cp.async.commit_group;" ::: "memory")
#define CP_WAIT(n)  asm volatile("cp.async.wait_group %0;" :: "n"(n) : "memory")

#define LDSM4(r, a)                                                                  \
    asm volatile("ldmatrix.sync.aligned.m8n8.x4.shared.b16 {%0,%1,%2,%3}, [%4];"     \
        : "=r"((r)[0]), "=r"((r)[1]), "=r"((r)[2]), "=r"((r)[3]) : "r"(a))

#define MMAB(d, a, b0, b1)                                                           \
    asm volatile("mma.sync.aligned.m16n8k16.row.col.f32.bf16.bf16.f32 "              \
        "{%0,%1,%2,%3}, {%4,%5,%6,%7}, {%8,%9}, {%0,%1,%2,%3};"                      \
        : "+f"((d)[0]), "+f"((d)[1]), "+f"((d)[2]), "+f"((d)[3])                     \
        : "r"((a)[0]), "r"((a)[1]), "r"((a)[2]), "r"((a)[3]), "r"(b0), "r"(b1))

// ======================= prepasses =======================
__global__ void absw_partial(const float* __restrict__ w) {
    float s = 0.f;
    const float4* w4 = (const float4*)w;
    int stride = gridDim.x * blockDim.x;
    for (int i = blockIdx.x * blockDim.x + threadIdx.x; i < W_ELEMS / 4; i += stride) {
        float4 v = w4[i];
        s += fabsf(v.x) + fabsf(v.y) + fabsf(v.z) + fabsf(v.w);
    }
    __shared__ float sh[8];
    #pragma unroll
    for (int o = 16; o; o >>= 1) s += __shfl_down_sync(0xFFFFFFFFu, s, o);
    if ((threadIdx.x & 31) == 0) sh[threadIdx.x >> 5] = s;
    __syncthreads();
    if (threadIdx.x == 0) {
        float t = 0.f;
        #pragma unroll
        for (int i = 0; i < 8; ++i) t += sh[i];
        g_partial[blockIdx.x] = t;
    }
}

__global__ void absw_final() {
    float s = 0.f;
    for (int i = threadIdx.x; i < 2048; i += 1024) s += g_partial[i];
    __shared__ float sh[32];
    #pragma unroll
    for (int o = 16; o; o >>= 1) s += __shfl_down_sync(0xFFFFFFFFu, s, o);
    if ((threadIdx.x & 31) == 0) sh[threadIdx.x >> 5] = s;
    __syncthreads();
    if (threadIdx.x == 0) {
        float t = 0.f;
        #pragma unroll
        for (int i = 0; i < 32; ++i) t += sh[i];
        g_gamma = fmaxf(t / (float)W_ELEMS, 1e-5f);
    }
}

__global__ void quant_w(const float* __restrict__ w) {
    float inv_g = 1.0f / g_gamma;
    const float4* w4 = (const float4*)w;
    uint2* out = (uint2*)g_wb;
    int stride = gridDim.x * blockDim.x;
    for (int i = blockIdx.x * blockDim.x + threadIdx.x; i < W_ELEMS / 4; i += stride) {
        float4 v = w4[i];
        float b0 = rintf(fminf(fmaxf(v.x * inv_g, -1.f), 1.f));
        float b1 = rintf(fminf(fmaxf(v.y * inv_g, -1.f), 1.f));
        float b2 = rintf(fminf(fmaxf(v.z * inv_g, -1.f), 1.f));
        float b3 = rintf(fminf(fmaxf(v.w * inv_g, -1.f), 1.f));
        __nv_bfloat162 p0 = __floats2bfloat162_rn(b0, b1);
        __nv_bfloat162 p1 = __floats2bfloat162_rn(b2, b3);
        out[i] = make_uint2(*(uint32_t*)&p0, *(uint32_t*)&p1);
    }
}

// LayerNorm + quant, single fused reduction round:
// sum/sumsq/min/max reduced together; eta = max(xmax-mean, mean-xmin)*rstd
// (bit-identical to per-element max|{(x-mean)*rstd}| by monotonicity).
__global__ void ln_quant_x(const float* __restrict__ x) {
    int row = blockIdx.x;
    const float4* xr = (const float4*)(x + (size_t)row * K_DIM);
    int tid = threadIdx.x;

    float4 p0 = xr[tid];
    float4 p1 = xr[tid + 256];
    float v[8] = {p0.x, p0.y, p0.z, p0.w, p1.x, p1.y, p1.z, p1.w};

    float s = 0.f, ss = 0.f, mx = -3.4e38f, mn = 3.4e38f;
    #pragma unroll
    for (int i = 0; i < 8; ++i) {
        s += v[i];
        ss += v[i] * v[i];
        mx = fmaxf(mx, v[i]);
        mn = fminf(mn, v[i]);
    }

    __shared__ float sh_s[8], sh_ss[8], sh_mx[8], sh_mn[8];
    #pragma unroll
    for (int o = 16; o; o >>= 1) {
        s  += __shfl_down_sync(0xFFFFFFFFu, s, o);
        ss += __shfl_down_sync(0xFFFFFFFFu, ss, o);
        mx  = fmaxf(mx, __shfl_down_sync(0xFFFFFFFFu, mx, o));
        mn  = fminf(mn, __shfl_down_sync(0xFFFFFFFFu, mn, o));
    }
    if ((tid & 31) == 0) {
        int w = tid >> 5;
        sh_s[w] = s; sh_ss[w] = ss; sh_mx[w] = mx; sh_mn[w] = mn;
    }
    __syncthreads();
    float s_tot = 0.f, ss_tot = 0.f, mx_t = -3.4e38f, mn_t = 3.4e38f;
    #pragma unroll
    for (int i = 0; i < 8; ++i) {
        s_tot += sh_s[i];
        ss_tot += sh_ss[i];
        mx_t = fmaxf(mx_t, sh_mx[i]);
        mn_t = fminf(mn_t, sh_mn[i]);
    }

    float mean = s_tot * (1.0f / K_DIM);
    float var  = fmaxf(ss_tot * (1.0f / K_DIM) - mean * mean, 0.0f);
    float rstd = rsqrtf(var + 1e-5f);
    float eta  = fmaxf(fmaxf((mx_t - mean) * rstd, (mean - mn_t) * rstd), 1e-5f);

    float q = 127.0f / eta;
    float b[8];
    #pragma unroll
    for (int i = 0; i < 8; ++i)
        b[i] = rintf(fminf(fmaxf((v[i] - mean) * rstd * q, -128.f), 127.f));

    __nv_bfloat162 q0 = __floats2bfloat162_rn(b[0], b[1]);
    __nv_bfloat162 q1 = __floats2bfloat162_rn(b[2], b[3]);
    __nv_bfloat162 q2 = __floats2bfloat162_rn(b[4], b[5]);
    __nv_bfloat162 q3 = __floats2bfloat162_rn(b[6], b[7]);
    uint2* xq = (uint2*)(g_xb + (size_t)row * K_DIM);
    xq[tid]       = make_uint2(*(uint32_t*)&q0, *(uint32_t*)&q1);
    xq[tid + 256] = make_uint2(*(uint32_t*)&q2, *(uint32_t*)&q3);

    if (tid == 0) g_scale[row] = g_gamma * eta * (1.0f / 127.0f);
}

// ======================= bf16 tensor-core GEMM =======================
// 256 threads = 8 warps in 2(m) x 4(n); warp tile 64x32; 2 CTAs per SM.
__global__ void __launch_bounds__(256, 2) gemm_hmma(float* __restrict__ out) {
    extern __shared__ char smem[];
    uint32_t sb = (smem_u32(smem) + 1023u) & ~1023u;

    const int tid  = threadIdx.x;
    const int lane = tid & 31;
    const int wid  = tid >> 5;
    const int wm   = wid >> 2;        // 0..1 (64 rows each)
    const int wn   = wid & 3;         // 0..3 (32 cols each)
    const int bx   = blockIdx.x;
    const int by   = blockIdx.y;

    const char* asrc0 = (const char*)(g_xb + (size_t)(by * BM) * K_DIM);
    const char* bsrc0 = (const char*)(g_wb + (size_t)(bx * BN) * K_DIM);

    const int lrow = lane & 15;
    const int lhi  = (lane & 16);

    float acc[4][4][4];
    #pragma unroll
    for (int mf = 0; mf < 4; ++mf)
        #pragma unroll
        for (int nf = 0; nf < 4; ++nf)
            #pragma unroll
            for (int r = 0; r < 4; ++r) acc[mf][nf][r] = 0.f;

    // ---- stage loader: 2048 x 16B, 8 per thread ----
    auto load_stage = [&](int s, int chunk) {
        uint32_t abase = sb + s * STAGE_BYTES;
        uint32_t bbase = abase + A_BYTES;
        const char* asrc = asrc0 + chunk * (BK * 2);
        const char* bsrc = bsrc0 + chunk * (BK * 2);
        #pragma unroll
        for (int j = 0; j < 8; ++j) {
            int t = tid + j * 256;
            if (t < 1024) {
                int row = t >> 3, seg = t & 7;
                cp16(abase + SW128(row * 128 + seg * 16),
                     asrc + (size_t)row * (K_DIM * 2) + seg * 16);
            } else {
                int u = t - 1024;
                int row = u >> 3, seg = u & 7;
                cp16(bbase + SW128(row * 128 + seg * 16),
                     bsrc + (size_t)row * (K_DIM * 2) + seg * 16);
            }
        }
    };

    load_stage(0, 0);
    CP_COMMIT();
    load_stage(1, 1);
    CP_COMMIT();

    const int arow0 = wm * 64 + lrow;          // + mf*16
    const int brow0 = wn * 32 + lrow;          // + nf2*16

    #pragma unroll 1
    for (int i = 0; i < CHUNKS; ++i) {
        CP_WAIT(1);
        __syncthreads();

        if (i + 2 < CHUNKS)
            load_stage((i + 2) % STAGES, i + 2);
        CP_COMMIT();

        uint32_t abase = sb + (i % STAGES) * STAGE_BYTES;
        uint32_t bbase = abase + A_BYTES;

        #pragma unroll
        for (int ks = 0; ks < 4; ++ks) {
            uint32_t a[4][4], b[2][4];
            #pragma unroll
            for (int mf = 0; mf < 4; ++mf)
                LDSM4(a[mf], abase + SW128((arow0 + mf * 16) * 128 + ks * 32 + lhi));
            #pragma unroll
            for (int nf2 = 0; nf2 < 2; ++nf2)
                LDSM4(b[nf2], bbase + SW128((brow0 + nf2 * 16) * 128 + ks * 32 + lhi));
            #pragma unroll
            for (int mf = 0; mf < 4; ++mf)
                #pragma unroll
                for (int nf2 = 0; nf2 < 2; ++nf2) {
                    MMAB(acc[mf][2 * nf2],     a[mf], b[nf2][0], b[nf2][2]);
                    MMAB(acc[mf][2 * nf2 + 1], a[mf], b[nf2][1], b[nf2][3]);
                }
        }
    }

    // ---- epilogue: scale by g_scale[m], write float2 ----
    const int row0 = by * BM + wm * 64;
    const int col0 = bx * BN + wn * 32;
    const int rq = lane >> 2;
    const int cq = (lane & 3) * 2;
    #pragma unroll
    for (int mf = 0; mf < 4; ++mf) {
        int r = row0 + mf * 16 + rq;
        float s0 = g_scale[r];
        float s1 = g_scale[r + 8];
        float* p0 = out + (size_t)r * N_OUT + col0 + cq;
        float* p1 = out + (size_t)(r + 8) * N_OUT + col0 + cq;
        #pragma unroll
        for (int nf = 0; nf < 4; ++nf) {
            float2 o0 = make_float2(acc[mf][nf][0] * s0, acc[mf][nf][1] * s0);
            float2 o1 = make_float2(acc[mf][nf][2] * s1, acc[mf][nf][3] * s1);
            *(float2*)(p0 + nf * 8) = o0;
            *(float2*)(p1 + nf * 8) = o1;
        }
    }
}

// ======================= launch =======================
extern "C" void kernel_launch(void* const* d_in, const int* in_sizes, int n_in,
                              void* d_out, int out_size) {
    const float* x = (const float*)d_in[0];
    const float* w = (const float*)d_in[1];
    float* out = (float*)d_out;

    cudaFuncSetAttribute(gemm_hmma, cudaFuncAttributeMaxDynamicSharedMemorySize, SMEM_TOTAL);

    absw_partial<<<2048, 256>>>(w);
    absw_final<<<1, 1024>>>();
    quant_w<<<4096, 256>>>(w);
    ln_quant_x<<<M_TOK, 256>>>(x);
    gemm_hmma<<<dim3(N_OUT / BN, M_TOK / BM), 256, SMEM_TOTAL>>>(out);
}

// round 12
// speedup vs baseline: 1.0053x; 1.0053x over previous
#include <cuda_runtime.h>
#include <cuda_bf16.h>
#include <cstdint>

// Shapes: x (4,2048,2048) -> M=8192, K=2048; weight (8192,2048) -> N=8192.
#define M_TOK 8192
#define K_DIM 2048
#define N_OUT 8192
#define W_ELEMS (N_OUT * K_DIM)
#define X_ELEMS (M_TOK * K_DIM)

// GEMM tiling (bf16: BK=64 elems = 128 bytes per SMEM row)
#define BM 128
#define BN 128
#define BK 64
#define CHUNKS (K_DIM / BK)          // 32
#define STAGES 3
#define A_BYTES (BM * 128)           // 16384
#define B_BYTES (BN * 128)           // 16384
#define STAGE_BYTES (A_BYTES + B_BYTES)   // 32768
#define SMEM_TOTAL (1024 + STAGES * STAGE_BYTES)   // 99328 -> 2 CTAs/SM

// ---- device scratch ----
__device__ float g_gamma;
__device__ float g_partial[2048];
__device__ float g_eta[M_TOK];            // eta/127 per token (gamma applied in GEMM)
__device__ __nv_bfloat16 g_xb[X_ELEMS];
__device__ __nv_bfloat16 g_wb[W_ELEMS];

// ======================= helpers =======================
__device__ __forceinline__ uint32_t smem_u32(const void* p) {
    uint32_t a;
    asm("{ .reg .u64 t; cvta.to.shared.u64 t, %1; cvt.u32.u64 %0, t; }" : "=r"(a) : "l"(p));
    return a;
}
#define SW128(o) ((o) ^ (((o) >> 3) & 0x70))

__device__ __forceinline__ void cp16(uint32_t dst, const void* src) {
    asm volatile("cp.async.cg.shared.global [%0], [%1], 16;" :: "r"(dst), "l"(src));
}
#define CP_COMMIT() asm volatile("cp.async.commit_group;" ::: "memory")
#define CP_WAIT(n)  asm volatile("cp.async.wait_group %0;" :: "n"(n) : "memory")

#define LDSM4(r, a)                                                                  \
    asm volatile("ldmatrix.sync.aligned.m8n8.x4.shared.b16 {%0,%1,%2,%3}, [%4];"     \
        : "=r"((r)[0]), "=r"((r)[1]), "=r"((r)[2]), "=r"((r)[3]) : "r"(a))

#define MMAB(d, a, b0, b1)                                                           \
    asm volatile("mma.sync.aligned.m16n8k16.row.col.f32.bf16.bf16.f32 "              \
        "{%0,%1,%2,%3}, {%4,%5,%6,%7}, {%8,%9}, {%0,%1,%2,%3};"                      \
        : "+f"((d)[0]), "+f"((d)[1]), "+f"((d)[2]), "+f"((d)[3])                     \
        : "r"((a)[0]), "r"((a)[1]), "r"((a)[2]), "r"((a)[3]), "r"(b0), "r"(b1))

// ======================= prepasses =======================
__global__ void absw_partial(const float* __restrict__ w) {
    float s = 0.f;
    const float4* w4 = (const float4*)w;
    int stride = gridDim.x * blockDim.x;
    for (int i = blockIdx.x * blockDim.x + threadIdx.x; i < W_ELEMS / 4; i += stride) {
        float4 v = w4[i];
        s += fabsf(v.x) + fabsf(v.y) + fabsf(v.z) + fabsf(v.w);
    }
    __shared__ float sh[8];
    #pragma unroll
    for (int o = 16; o; o >>= 1) s += __shfl_down_sync(0xFFFFFFFFu, s, o);
    if ((threadIdx.x & 31) == 0) sh[threadIdx.x >> 5] = s;
    __syncthreads();
    if (threadIdx.x == 0) {
        float t = 0.f;
        #pragma unroll
        for (int i = 0; i < 8; ++i) t += sh[i];
        g_partial[blockIdx.x] = t;
    }
}

// quant_w with the gamma final-reduction folded in (every block computes the
// identical deterministic reduction of g_partial; block 0 publishes g_gamma
// for the GEMM epilogue).
__global__ void quant_w(const float* __restrict__ w) {
    // per-block reduction of the 2048 partials (identical in every block)
    __shared__ float sh[8];
    {
        float s = 0.f;
        #pragma unroll
        for (int j = 0; j < 8; ++j) s += g_partial[threadIdx.x + j * 256];
        #pragma unroll
        for (int o = 16; o; o >>= 1) s += __shfl_down_sync(0xFFFFFFFFu, s, o);
        if ((threadIdx.x & 31) == 0) sh[threadIdx.x >> 5] = s;
    }
    __syncthreads();
    float t = 0.f;
    #pragma unroll
    for (int i = 0; i < 8; ++i) t += sh[i];
    float gamma = fmaxf(t / (float)W_ELEMS, 1e-5f);
    float inv_g = 1.0f / gamma;

    if (blockIdx.x == 0 && threadIdx.x == 0) g_gamma = gamma;

    const float4* w4 = (const float4*)w;
    uint2* out = (uint2*)g_wb;
    int stride = gridDim.x * blockDim.x;
    for (int i = blockIdx.x * blockDim.x + threadIdx.x; i < W_ELEMS / 4; i += stride) {
        float4 v = w4[i];
        float b0 = rintf(fminf(fmaxf(v.x * inv_g, -1.f), 1.f));
        float b1 = rintf(fminf(fmaxf(v.y * inv_g, -1.f), 1.f));
        float b2 = rintf(fminf(fmaxf(v.z * inv_g, -1.f), 1.f));
        float b3 = rintf(fminf(fmaxf(v.w * inv_g, -1.f), 1.f));
        __nv_bfloat162 p0 = __floats2bfloat162_rn(b0, b1);
        __nv_bfloat162 p1 = __floats2bfloat162_rn(b2, b3);
        out[i] = make_uint2(*(uint32_t*)&p0, *(uint32_t*)&p1);
    }
}

// LayerNorm + per-token absmax quant (R9 two-phase numerics).
// Stores eta/127 only; gamma is applied in the GEMM epilogue.
__global__ void ln_quant_x(const float* __restrict__ x) {
    int row = blockIdx.x;
    const float4* xr = (const float4*)(x + (size_t)row * K_DIM);
    int tid = threadIdx.x;

    float4 p0 = xr[tid];
    float4 p1 = xr[tid + 256];
    float v[8] = {p0.x, p0.y, p0.z, p0.w, p1.x, p1.y, p1.z, p1.w};

    float s = 0.f, ss = 0.f;
    #pragma unroll
    for (int i = 0; i < 8; ++i) { s += v[i]; ss += v[i] * v[i]; }

    __shared__ float sh_s[8], sh_ss[8], sh_m[8];
    #pragma unroll
    for (int o = 16; o; o >>= 1) {
        s  += __shfl_down_sync(0xFFFFFFFFu, s, o);
        ss += __shfl_down_sync(0xFFFFFFFFu, ss, o);
    }
    if ((tid & 31) == 0) { sh_s[tid >> 5] = s; sh_ss[tid >> 5] = ss; }
    __syncthreads();
    float s_tot = 0.f, ss_tot = 0.f;
    #pragma unroll
    for (int i = 0; i < 8; ++i) { s_tot += sh_s[i]; ss_tot += sh_ss[i]; }

    float mean = s_tot * (1.0f / K_DIM);
    float var  = fmaxf(ss_tot * (1.0f / K_DIM) - mean * mean, 0.0f);
    float rstd = rsqrtf(var + 1e-5f);

    float mx = 0.f;
    #pragma unroll
    for (int i = 0; i < 8; ++i) {
        v[i] = (v[i] - mean) * rstd;
        mx = fmaxf(mx, fabsf(v[i]));
    }
    #pragma unroll
    for (int o = 16; o; o >>= 1) mx = fmaxf(mx, __shfl_down_sync(0xFFFFFFFFu, mx, o));
    if ((tid & 31) == 0) sh_m[tid >> 5] = mx;
    __syncthreads();
    float eta = 1e-5f;
    #pragma unroll
    for (int i = 0; i < 8; ++i) eta = fmaxf(eta, sh_m[i]);

    float q = 127.0f / eta;
    float b[8];
    #pragma unroll
    for (int i = 0; i < 8; ++i)
        b[i] = rintf(fminf(fmaxf(v[i] * q, -128.f), 127.f));

    __nv_bfloat162 q0 = __floats2bfloat162_rn(b[0], b[1]);
    __nv_bfloat162 q1 = __floats2bfloat162_rn(b[2], b[3]);
    __nv_bfloat162 q2 = __floats2bfloat162_rn(b[4], b[5]);
    __nv_bfloat162 q3 = __floats2bfloat162_rn(b[6], b[7]);
    uint2* xq = (uint2*)(g_xb + (size_t)row * K_DIM);
    xq[tid]       = make_uint2(*(uint32_t*)&q0, *(uint32_t*)&q1);
    xq[tid + 256] = make_uint2(*(uint32_t*)&q2, *(uint32_t*)&q3);

    if (tid == 0) g_eta[row] = eta * (1.0f / 127.0f);
}

// ======================= bf16 tensor-core GEMM =======================
// 256 threads = 8 warps in 2(m) x 4(n); warp tile 64x32; 2 CTAs per SM.
__global__ void __launch_bounds__(256, 2) gemm_hmma(float* __restrict__ out) {
    extern __shared__ char smem[];
    uint32_t sb = (smem_u32(smem) + 1023u) & ~1023u;

    const int tid  = threadIdx.x;
    const int lane = tid & 31;
    const int wid  = tid >> 5;
    const int wm   = wid >> 2;        // 0..1 (64 rows each)
    const int wn   = wid & 3;         // 0..3 (32 cols each)
    const int bx   = blockIdx.x;
    const int by   = blockIdx.y;

    const char* asrc0 = (const char*)(g_xb + (size_t)(by * BM) * K_DIM);
    const char* bsrc0 = (const char*)(g_wb + (size_t)(bx * BN) * K_DIM);

    const int lrow = lane & 15;
    const int lhi  = (lane & 16);

    float acc[4][4][4];
    #pragma unroll
    for (int mf = 0; mf < 4; ++mf)
        #pragma unroll
        for (int nf = 0; nf < 4; ++nf)
            #pragma unroll
            for (int r = 0; r < 4; ++r) acc[mf][nf][r] = 0.f;

    auto load_stage = [&](int s, int chunk) {
        uint32_t abase = sb + s * STAGE_BYTES;
        uint32_t bbase = abase + A_BYTES;
        const char* asrc = asrc0 + chunk * (BK * 2);
        const char* bsrc = bsrc0 + chunk * (BK * 2);
        #pragma unroll
        for (int j = 0; j < 8; ++j) {
            int t = tid + j * 256;
            if (t < 1024) {
                int row = t >> 3, seg = t & 7;
                cp16(abase + SW128(row * 128 + seg * 16),
                     asrc + (size_t)row * (K_DIM * 2) + seg * 16);
            } else {
                int u = t - 1024;
                int row = u >> 3, seg = u & 7;
                cp16(bbase + SW128(row * 128 + seg * 16),
                     bsrc + (size_t)row * (K_DIM * 2) + seg * 16);
            }
        }
    };

    load_stage(0, 0);
    CP_COMMIT();
    load_stage(1, 1);
    CP_COMMIT();

    const int arow0 = wm * 64 + lrow;          // + mf*16
    const int brow0 = wn * 32 + lrow;          // + nf2*16

    #pragma unroll 1
    for (int i = 0; i < CHUNKS; ++i) {
        CP_WAIT(1);
        __syncthreads();

        if (i + 2 < CHUNKS)
            load_stage((i + 2) % STAGES, i + 2);
        CP_COMMIT();

        uint32_t abase = sb + (i % STAGES) * STAGE_BYTES;
        uint32_t bbase = abase + A_BYTES;

        #pragma unroll
        for (int ks = 0; ks < 4; ++ks) {
            uint32_t a[4][4], b[2][4];
            #pragma unroll
            for (int mf = 0; mf < 4; ++mf)
                LDSM4(a[mf], abase + SW128((arow0 + mf * 16) * 128 + ks * 32 + lhi));
            #pragma unroll
            for (int nf2 = 0; nf2 < 2; ++nf2)
                LDSM4(b[nf2], bbase + SW128((brow0 + nf2 * 16) * 128 + ks * 32 + lhi));
            #pragma unroll
            for (int mf = 0; mf < 4; ++mf)
                #pragma unroll
                for (int nf2 = 0; nf2 < 2; ++nf2) {
                    MMAB(acc[mf][2 * nf2],     a[mf], b[nf2][0], b[nf2][2]);
                    MMAB(acc[mf][2 * nf2 + 1], a[mf], b[nf2][1], b[nf2][3]);
                }
        }
    }

    // ---- epilogue: scale by gamma * eta/127, write float2 ----
    const float gamma = g_gamma;
    const int row0 = by * BM + wm * 64;
    const int col0 = bx * BN + wn * 32;
    const int rq = lane >> 2;
    const int cq = (lane & 3) * 2;
    #pragma unroll
    for (int mf = 0; mf < 4; ++mf) {
        int r = row0 + mf * 16 + rq;
        float s0 = gamma * g_eta[r];
        float s1 = gamma * g_eta[r + 8];
        float* p0 = out + (size_t)r * N_OUT + col0 + cq;
        float* p1 = out + (size_t)(r + 8) * N_OUT + col0 + cq;
        #pragma unroll
        for (int nf = 0; nf < 4; ++nf) {
            float2 o0 = make_float2(acc[mf][nf][0] * s0, acc[mf][nf][1] * s0);
            float2 o1 = make_float2(acc[mf][nf][2] * s1, acc[mf][nf][3] * s1);
            *(float2*)(p0 + nf * 8) = o0;
            *(float2*)(p1 + nf * 8) = o1;
        }
    }
}

// ======================= launch =======================
extern "C" void kernel_launch(void* const* d_in, const int* in_sizes, int n_in,
                              void* d_out, int out_size) {
    const float* x = (const float*)d_in[0];
    const float* w = (const float*)d_in[1];
    float* out = (float*)d_out;

    cudaFuncSetAttribute(gemm_hmma, cudaFuncAttributeMaxDynamicSharedMemorySize, SMEM_TOTAL);

    absw_partial<<<2048, 256>>>(w);
    ln_quant_x<<<M_TOK, 256>>>(x);       // independent of gamma now
    quant_w<<<4096, 256>>>(w);           // folds gamma final-reduce
    gemm_hmma<<<dim3(N_OUT / BN, M_TOK / BM), 256, SMEM_TOTAL>>>(out);
}

// round 13
// speedup vs baseline: 1.0095x; 1.0042x over previous
#include <cuda_runtime.h>
#include <cuda_bf16.h>
#include <cstdint>

// Shapes: x (4,2048,2048) -> M=8192, K=2048; weight (8192,2048) -> N=8192.
#define M_TOK 8192
#define K_DIM 2048
#define N_OUT 8192
#define W_ELEMS (N_OUT * K_DIM)
#define X_ELEMS (M_TOK * K_DIM)

// GEMM tiling (bf16: BK=64 elems = 128 bytes per SMEM row)
#define BM 128
#define BN 128
#define BK 64
#define CHUNKS (K_DIM / BK)          // 32
#define STAGES 3
#define A_BYTES (BM * 128)           // 16384
#define B_BYTES (BN * 128)           // 16384
#define STAGE_BYTES (A_BYTES + B_BYTES)   // 32768
#define SMEM_TOTAL (1024 + STAGES * STAGE_BYTES)   // 99328 -> 2 CTAs/SM

// ---- device scratch ----
__device__ float g_gamma;
__device__ float g_partial[8192];         // one |w| partial per LN block
__device__ float g_eta[M_TOK];            // eta/127 per token
__device__ __nv_bfloat16 g_xb[X_ELEMS];
__device__ __nv_bfloat16 g_wb[W_ELEMS];

// ======================= helpers =======================
__device__ __forceinline__ uint32_t smem_u32(const void* p) {
    uint32_t a;
    asm("{ .reg .u64 t; cvta.to.shared.u64 t, %1; cvt.u32.u64 %0, t; }" : "=r"(a) : "l"(p));
    return a;
}
#define SW128(o) ((o) ^ (((o) >> 3) & 0x70))

__device__ __forceinline__ void cp16(uint32_t dst, const void* src) {
    asm volatile("cp.async.cg.shared.global [%0], [%1], 16;" :: "r"(dst), "l"(src));
}
#define CP_COMMIT() asm volatile("cp.async.commit_group;" ::: "memory")
#define CP_WAIT(n)  asm volatile("cp.async.wait_group %0;" :: "n"(n) : "memory")

#define LDSM4(r, a)                                                                  \
    asm volatile("ldmatrix.sync.aligned.m8n8.x4.shared.b16 {%0,%1,%2,%3}, [%4];"     \
        : "=r"((r)[0]), "=r"((r)[1]), "=r"((r)[2]), "=r"((r)[3]) : "r"(a))

#define MMAB(d, a, b0, b1)                                                           \
    asm volatile("mma.sync.aligned.m16n8k16.row.col.f32.bf16.bf16.f32 "              \
        "{%0,%1,%2,%3}, {%4,%5,%6,%7}, {%8,%9}, {%0,%1,%2,%3};"                      \
        : "+f"((d)[0]), "+f"((d)[1]), "+f"((d)[2]), "+f"((d)[3])                     \
        : "r"((a)[0]), "r"((a)[1]), "r"((a)[2]), "r"((a)[3]), "r"(b0), "r"(b1))

// ======================= prepass 1: LN + x-quant + |w| partial =======================
// Block b: LayerNorm+quant of token row b, AND abs-sum of w[b*2048 .. b*2048+2047].
__global__ void ln_quant_x(const float* __restrict__ x, const float* __restrict__ w) {
    int row = blockIdx.x;
    int tid = threadIdx.x;
    const float4* xr = (const float4*)(x + (size_t)row * K_DIM);
    const float4* wr = (const float4*)w + (size_t)row * 512;

    float4 p0 = xr[tid];
    float4 p1 = xr[tid + 256];
    float4 w0 = wr[tid];
    float4 w1 = wr[tid + 256];
    float v[8] = {p0.x, p0.y, p0.z, p0.w, p1.x, p1.y, p1.z, p1.w};

    float s = 0.f, ss = 0.f;
    #pragma unroll
    for (int i = 0; i < 8; ++i) { s += v[i]; ss += v[i] * v[i]; }
    float wsum = fabsf(w0.x) + fabsf(w0.y) + fabsf(w0.z) + fabsf(w0.w)
               + fabsf(w1.x) + fabsf(w1.y) + fabsf(w1.z) + fabsf(w1.w);

    __shared__ float sh_s[8], sh_ss[8], sh_w[8], sh_m[8];
    #pragma unroll
    for (int o = 16; o; o >>= 1) {
        s    += __shfl_down_sync(0xFFFFFFFFu, s, o);
        ss   += __shfl_down_sync(0xFFFFFFFFu, ss, o);
        wsum += __shfl_down_sync(0xFFFFFFFFu, wsum, o);
    }
    if ((tid & 31) == 0) {
        int wi = tid >> 5;
        sh_s[wi] = s; sh_ss[wi] = ss; sh_w[wi] = wsum;
    }
    __syncthreads();
    float s_tot = 0.f, ss_tot = 0.f;
    #pragma unroll
    for (int i = 0; i < 8; ++i) { s_tot += sh_s[i]; ss_tot += sh_ss[i]; }
    if (tid == 0) {
        float wt = 0.f;
        #pragma unroll
        for (int i = 0; i < 8; ++i) wt += sh_w[i];
        g_partial[row] = wt;
    }

    float mean = s_tot * (1.0f / K_DIM);
    float var  = fmaxf(ss_tot * (1.0f / K_DIM) - mean * mean, 0.0f);
    float rstd = rsqrtf(var + 1e-5f);

    float mx = 0.f;
    #pragma unroll
    for (int i = 0; i < 8; ++i) {
        v[i] = (v[i] - mean) * rstd;
        mx = fmaxf(mx, fabsf(v[i]));
    }
    #pragma unroll
    for (int o = 16; o; o >>= 1) mx = fmaxf(mx, __shfl_down_sync(0xFFFFFFFFu, mx, o));
    if ((tid & 31) == 0) sh_m[tid >> 5] = mx;
    __syncthreads();
    float eta = 1e-5f;
    #pragma unroll
    for (int i = 0; i < 8; ++i) eta = fmaxf(eta, sh_m[i]);

    float q = 127.0f / eta;
    float b[8];
    #pragma unroll
    for (int i = 0; i < 8; ++i)
        b[i] = rintf(fminf(fmaxf(v[i] * q, -128.f), 127.f));

    __nv_bfloat162 q0 = __floats2bfloat162_rn(b[0], b[1]);
    __nv_bfloat162 q1 = __floats2bfloat162_rn(b[2], b[3]);
    __nv_bfloat162 q2 = __floats2bfloat162_rn(b[4], b[5]);
    __nv_bfloat162 q3 = __floats2bfloat162_rn(b[6], b[7]);
    uint2* xq = (uint2*)(g_xb + (size_t)row * K_DIM);
    xq[tid]       = make_uint2(*(uint32_t*)&q0, *(uint32_t*)&q1);
    xq[tid + 256] = make_uint2(*(uint32_t*)&q2, *(uint32_t*)&q3);

    if (tid == 0) g_eta[row] = eta * (1.0f / 127.0f);
}

// ======================= prepass 2: gamma reduce (folded) + w-quant =======================
// Every block (1024 threads) deterministically reduces the 8192 partials to the
// SAME gamma, then grid-strides the ternary quantization. Block 0 publishes g_gamma.
__global__ void quant_w(const float* __restrict__ w) {
    __shared__ float sh[32];
    __shared__ float sh_gamma;
    {
        float s = 0.f;
        #pragma unroll
        for (int j = 0; j < 8; ++j) s += g_partial[threadIdx.x + j * 1024];
        #pragma unroll
        for (int o = 16; o; o >>= 1) s += __shfl_down_sync(0xFFFFFFFFu, s, o);
        if ((threadIdx.x & 31) == 0) sh[threadIdx.x >> 5] = s;
    }
    __syncthreads();
    if (threadIdx.x == 0) {
        float t = 0.f;
        #pragma unroll
        for (int i = 0; i < 32; ++i) t += sh[i];
        float gm = fmaxf(t / (float)W_ELEMS, 1e-5f);
        sh_gamma = gm;
        if (blockIdx.x == 0) g_gamma = gm;
    }
    __syncthreads();
    float inv_g = 1.0f / sh_gamma;

    const float4* w4 = (const float4*)w;
    uint2* out = (uint2*)g_wb;
    int stride = gridDim.x * blockDim.x;
    for (int i = blockIdx.x * blockDim.x + threadIdx.x; i < W_ELEMS / 4; i += stride) {
        float4 v = w4[i];
        float b0 = rintf(fminf(fmaxf(v.x * inv_g, -1.f), 1.f));
        float b1 = rintf(fminf(fmaxf(v.y * inv_g, -1.f), 1.f));
        float b2 = rintf(fminf(fmaxf(v.z * inv_g, -1.f), 1.f));
        float b3 = rintf(fminf(fmaxf(v.w * inv_g, -1.f), 1.f));
        __nv_bfloat162 p0 = __floats2bfloat162_rn(b0, b1);
        __nv_bfloat162 p1 = __floats2bfloat162_rn(b2, b3);
        out[i] = make_uint2(*(uint32_t*)&p0, *(uint32_t*)&p1);
    }
}

// ======================= bf16 tensor-core GEMM (frozen R9/R12 config) =======================
// 256 threads = 8 warps in 2(m) x 4(n); warp tile 64x32; 2 CTAs per SM.
__global__ void __launch_bounds__(256, 2) gemm_hmma(float* __restrict__ out) {
    extern __shared__ char smem[];
    uint32_t sb = (smem_u32(smem) + 1023u) & ~1023u;

    const int tid  = threadIdx.x;
    const int lane = tid & 31;
    const int wid  = tid >> 5;
    const int wm   = wid >> 2;        // 0..1 (64 rows each)
    const int wn   = wid & 3;         // 0..3 (32 cols each)
    const int bx   = blockIdx.x;
    const int by   = blockIdx.y;

    const char* asrc0 = (const char*)(g_xb + (size_t)(by * BM) * K_DIM);
    const char* bsrc0 = (const char*)(g_wb + (size_t)(bx * BN) * K_DIM);

    const int lrow = lane & 15;
    const int lhi  = (lane & 16);

    float acc[4][4][4];
    #pragma unroll
    for (int mf = 0; mf < 4; ++mf)
        #pragma unroll
        for (int nf = 0; nf < 4; ++nf)
            #pragma unroll
            for (int r = 0; r < 4; ++r) acc[mf][nf][r] = 0.f;

    auto load_stage = [&](int s, int chunk) {
        uint32_t abase = sb + s * STAGE_BYTES;
        uint32_t bbase = abase + A_BYTES;
        const char* asrc = asrc0 + chunk * (BK * 2);
        const char* bsrc = bsrc0 + chunk * (BK * 2);
        #pragma unroll
        for (int j = 0; j < 8; ++j) {
            int t = tid + j * 256;
            if (t < 1024) {
                int row = t >> 3, seg = t & 7;
                cp16(abase + SW128(row * 128 + seg * 16),
                     asrc + (size_t)row * (K_DIM * 2) + seg * 16);
            } else {
                int u = t - 1024;
                int row = u >> 3, seg = u & 7;
                cp16(bbase + SW128(row * 128 + seg * 16),
                     bsrc + (size_t)row * (K_DIM * 2) + seg * 16);
            }
        }
    };

    load_stage(0, 0);
    CP_COMMIT();
    load_stage(1, 1);
    CP_COMMIT();

    const int arow0 = wm * 64 + lrow;          // + mf*16
    const int brow0 = wn * 32 + lrow;          // + nf2*16

    #pragma unroll 1
    for (int i = 0; i < CHUNKS; ++i) {
        CP_WAIT(1);
        __syncthreads();

        if (i + 2 < CHUNKS)
            load_stage((i + 2) % STAGES, i + 2);
        CP_COMMIT();

        uint32_t abase = sb + (i % STAGES) * STAGE_BYTES;
        uint32_t bbase = abase + A_BYTES;

        #pragma unroll
        for (int ks = 0; ks < 4; ++ks) {
            uint32_t a[4][4], b[2][4];
            #pragma unroll
            for (int mf = 0; mf < 4; ++mf)
                LDSM4(a[mf], abase + SW128((arow0 + mf * 16) * 128 + ks * 32 + lhi));
            #pragma unroll
            for (int nf2 = 0; nf2 < 2; ++nf2)
                LDSM4(b[nf2], bbase + SW128((brow0 + nf2 * 16) * 128 + ks * 32 + lhi));
            #pragma unroll
            for (int mf = 0; mf < 4; ++mf)
                #pragma unroll
                for (int nf2 = 0; nf2 < 2; ++nf2) {
                    MMAB(acc[mf][2 * nf2],     a[mf], b[nf2][0], b[nf2][2]);
                    MMAB(acc[mf][2 * nf2 + 1], a[mf], b[nf2][1], b[nf2][3]);
                }
        }
    }

    // ---- epilogue: scale by gamma * eta/127, write float2 ----
    const float gamma = g_gamma;
    const int row0 = by * BM + wm * 64;
    const int col0 = bx * BN + wn * 32;
    const int rq = lane >> 2;
    const int cq = (lane & 3) * 2;
    #pragma unroll
    for (int mf = 0; mf < 4; ++mf) {
        int r = row0 + mf * 16 + rq;
        float s0 = gamma * g_eta[r];
        float s1 = gamma * g_eta[r + 8];
        float* p0 = out + (size_t)r * N_OUT + col0 + cq;
        float* p1 = out + (size_t)(r + 8) * N_OUT + col0 + cq;
        #pragma unroll
        for (int nf = 0; nf < 4; ++nf) {
            float2 o0 = make_float2(acc[mf][nf][0] * s0, acc[mf][nf][1] * s0);
            float2 o1 = make_float2(acc[mf][nf][2] * s1, acc[mf][nf][3] * s1);
            *(float2*)(p0 + nf * 8) = o0;
            *(float2*)(p1 + nf * 8) = o1;
        }
    }
}

// ======================= launch (3 kernels) =======================
extern "C" void kernel_launch(void* const* d_in, const int* in_sizes, int n_in,
                              void* d_out, int out_size) {
    const float* x = (const float*)d_in[0];
    const float* w = (const float*)d_in[1];
    float* out = (float*)d_out;

    cudaFuncSetAttribute(gemm_hmma, cudaFuncAttributeMaxDynamicSharedMemorySize, SMEM_TOTAL);

    ln_quant_x<<<M_TOK, 256>>>(x, w);    // LN + x-quant + |w| partials
    quant_w<<<1024, 1024>>>(w);          // gamma reduce (folded) + w-quant
    gemm_hmma<<<dim3(N_OUT / BN, M_TOK / BM), 256, SMEM_TOTAL>>>(out);
}

// round 14
// speedup vs baseline: 1.0122x; 1.0026x over previous
#include <cuda_runtime.h>
#include <cuda_bf16.h>
#include <cstdint>

// Shapes: x (4,2048,2048) -> M=8192, K=2048; weight (8192,2048) -> N=8192.
#define M_TOK 8192
#define K_DIM 2048
#define N_OUT 8192
#define W_ELEMS (N_OUT * K_DIM)
#define X_ELEMS (M_TOK * K_DIM)

// GEMM tiling (bf16: BK=64 elems = 128 bytes per SMEM row)
#define BM 128
#define BN 128
#define BK 64
#define CHUNKS (K_DIM / BK)          // 32
#define STAGES 3
#define A_BYTES (BM * 128)           // 16384
#define B_BYTES (BN * 128)           // 16384
#define STAGE_BYTES (A_BYTES + B_BYTES)   // 32768
#define SMEM_TOTAL (1024 + STAGES * STAGE_BYTES)   // 99328 -> 2 CTAs/SM

// ---- device scratch ----
__device__ float g_gamma;
__device__ float g_partial[8192];         // one |w| partial per LN block
__device__ float g_eta[M_TOK];            // eta/127 per token
__device__ __nv_bfloat16 g_xb[X_ELEMS];
__device__ __nv_bfloat16 g_wb[W_ELEMS];

// ======================= helpers =======================
__device__ __forceinline__ uint32_t smem_u32(const void* p) {
    uint32_t a;
    asm("{ .reg .u64 t; cvta.to.shared.u64 t, %1; cvt.u32.u64 %0, t; }" : "=r"(a) : "l"(p));
    return a;
}
#define SW128(o) ((o) ^ (((o) >> 3) & 0x70))

__device__ __forceinline__ void cp16(uint32_t dst, const void* src) {
    asm volatile("cp.async.cg.shared.global [%0], [%1], 16;" :: "r"(dst), "l"(src));
}
#define CP_COMMIT() asm volatile("cp.async.commit_group;" ::: "memory")
#define CP_WAIT(n)  asm volatile("cp.async.wait_group %0;" :: "n"(n) : "memory")

#define LDSM4(r, a)                                                                  \
    asm volatile("ldmatrix.sync.aligned.m8n8.x4.shared.b16 {%0,%1,%2,%3}, [%4];"     \
        : "=r"((r)[0]), "=r"((r)[1]), "=r"((r)[2]), "=r"((r)[3]) : "r"(a))

#define MMAB(d, a, b0, b1)                                                           \
    asm volatile("mma.sync.aligned.m16n8k16.row.col.f32.bf16.bf16.f32 "              \
        "{%0,%1,%2,%3}, {%4,%5,%6,%7}, {%8,%9}, {%0,%1,%2,%3};"                      \
        : "+f"((d)[0]), "+f"((d)[1]), "+f"((d)[2]), "+f"((d)[3])                     \
        : "r"((a)[0]), "r"((a)[1]), "r"((a)[2]), "r"((a)[3]), "r"(b0), "r"(b1))

// ======================= prepass 1: LN + x-quant + |w| partial =======================
// Block b: LayerNorm+quant of token row b (x streamed with evict-first so w
// stays L2-resident for quant_w), AND abs-sum of w[b*2048 .. +2047].
__global__ void ln_quant_x(const float* __restrict__ x, const float* __restrict__ w) {
    int row = blockIdx.x;
    int tid = threadIdx.x;
    const float4* xr = (const float4*)(x + (size_t)row * K_DIM);
    const float4* wr = (const float4*)w + (size_t)row * 512;

    float4 p0 = __ldcs(xr + tid);            // streaming: x is read exactly once
    float4 p1 = __ldcs(xr + tid + 256);
    float4 w0 = wr[tid];                     // w will be re-read by quant_w: keep in L2
    float4 w1 = wr[tid + 256];
    float v[8] = {p0.x, p0.y, p0.z, p0.w, p1.x, p1.y, p1.z, p1.w};

    float s = 0.f, ss = 0.f;
    #pragma unroll
    for (int i = 0; i < 8; ++i) { s += v[i]; ss += v[i] * v[i]; }
    float wsum = fabsf(w0.x) + fabsf(w0.y) + fabsf(w0.z) + fabsf(w0.w)
               + fabsf(w1.x) + fabsf(w1.y) + fabsf(w1.z) + fabsf(w1.w);

    __shared__ float sh_s[8], sh_ss[8], sh_w[8], sh_m[8];
    #pragma unroll
    for (int o = 16; o; o >>= 1) {
        s    += __shfl_down_sync(0xFFFFFFFFu, s, o);
        ss   += __shfl_down_sync(0xFFFFFFFFu, ss, o);
        wsum += __shfl_down_sync(0xFFFFFFFFu, wsum, o);
    }
    if ((tid & 31) == 0) {
        int wi = tid >> 5;
        sh_s[wi] = s; sh_ss[wi] = ss; sh_w[wi] = wsum;
    }
    __syncthreads();
    float s_tot = 0.f, ss_tot = 0.f;
    #pragma unroll
    for (int i = 0; i < 8; ++i) { s_tot += sh_s[i]; ss_tot += sh_ss[i]; }
    if (tid == 0) {
        float wt = 0.f;
        #pragma unroll
        for (int i = 0; i < 8; ++i) wt += sh_w[i];
        g_partial[row] = wt;
    }

    float mean = s_tot * (1.0f / K_DIM);
    float var  = fmaxf(ss_tot * (1.0f / K_DIM) - mean * mean, 0.0f);
    float rstd = rsqrtf(var + 1e-5f);

    float mx = 0.f;
    #pragma unroll
    for (int i = 0; i < 8; ++i) {
        v[i] = (v[i] - mean) * rstd;
        mx = fmaxf(mx, fabsf(v[i]));
    }
    #pragma unroll
    for (int o = 16; o; o >>= 1) mx = fmaxf(mx, __shfl_down_sync(0xFFFFFFFFu, mx, o));
    if ((tid & 31) == 0) sh_m[tid >> 5] = mx;
    __syncthreads();
    float eta = 1e-5f;
    #pragma unroll
    for (int i = 0; i < 8; ++i) eta = fmaxf(eta, sh_m[i]);

    float q = 127.0f / eta;
    float b[8];
    #pragma unroll
    for (int i = 0; i < 8; ++i)
        b[i] = rintf(fminf(fmaxf(v[i] * q, -128.f), 127.f));

    __nv_bfloat162 q0 = __floats2bfloat162_rn(b[0], b[1]);
    __nv_bfloat162 q1 = __floats2bfloat162_rn(b[2], b[3]);
    __nv_bfloat162 q2 = __floats2bfloat162_rn(b[4], b[5]);
    __nv_bfloat162 q3 = __floats2bfloat162_rn(b[6], b[7]);
    uint2* xq = (uint2*)(g_xb + (size_t)row * K_DIM);
    xq[tid]       = make_uint2(*(uint32_t*)&q0, *(uint32_t*)&q1);
    xq[tid + 256] = make_uint2(*(uint32_t*)&q2, *(uint32_t*)&q3);

    if (tid == 0) g_eta[row] = eta * (1.0f / 127.0f);
}

// ======================= prepass 2: gamma reduce (folded) + w-quant =======================
// Every block (256 threads) deterministically reduces the 8192 partials to the
// SAME gamma, then grid-strides the ternary quantization. Block 0 publishes g_gamma.
__global__ void quant_w(const float* __restrict__ w) {
    __shared__ float sh[8];
    __shared__ float sh_gamma;
    {
        float s = 0.f;
        #pragma unroll
        for (int j = 0; j < 32; ++j) s += g_partial[threadIdx.x + j * 256];
        #pragma unroll
        for (int o = 16; o; o >>= 1) s += __shfl_down_sync(0xFFFFFFFFu, s, o);
        if ((threadIdx.x & 31) == 0) sh[threadIdx.x >> 5] = s;
    }
    __syncthreads();
    if (threadIdx.x == 0) {
        float t = 0.f;
        #pragma unroll
        for (int i = 0; i < 8; ++i) t += sh[i];
        float gm = fmaxf(t / (float)W_ELEMS, 1e-5f);
        sh_gamma = gm;
        if (blockIdx.x == 0) g_gamma = gm;
    }
    __syncthreads();
    float inv_g = 1.0f / sh_gamma;

    const float4* w4 = (const float4*)w;
    uint2* out = (uint2*)g_wb;
    int stride = gridDim.x * blockDim.x;
    for (int i = blockIdx.x * blockDim.x + threadIdx.x; i < W_ELEMS / 4; i += stride) {
        float4 v = w4[i];
        float b0 = rintf(fminf(fmaxf(v.x * inv_g, -1.f), 1.f));
        float b1 = rintf(fminf(fmaxf(v.y * inv_g, -1.f), 1.f));
        float b2 = rintf(fminf(fmaxf(v.z * inv_g, -1.f), 1.f));
        float b3 = rintf(fminf(fmaxf(v.w * inv_g, -1.f), 1.f));
        __nv_bfloat162 p0 = __floats2bfloat162_rn(b0, b1);
        __nv_bfloat162 p1 = __floats2bfloat162_rn(b2, b3);
        out[i] = make_uint2(*(uint32_t*)&p0, *(uint32_t*)&p1);
    }
}

// ======================= bf16 tensor-core GEMM (frozen R9/R12 config) =======================
// 256 threads = 8 warps in 2(m) x 4(n); warp tile 64x32; 2 CTAs per SM.
__global__ void __launch_bounds__(256, 2) gemm_hmma(float* __restrict__ out) {
    extern __shared__ char smem[];
    uint32_t sb = (smem_u32(smem) + 1023u) & ~1023u;

    const int tid  = threadIdx.x;
    const int lane = tid & 31;
    const int wid  = tid >> 5;
    const int wm   = wid >> 2;        // 0..1 (64 rows each)
    const int wn   = wid & 3;         // 0..3 (32 cols each)
    const int bx   = blockIdx.x;
    const int by   = blockIdx.y;

    const char* asrc0 = (const char*)(g_xb + (size_t)(by * BM) * K_DIM);
    const char* bsrc0 = (const char*)(g_wb + (size_t)(bx * BN) * K_DIM);

    const int lrow = lane & 15;
    const int lhi  = (lane & 16);

    float acc[4][4][4];
    #pragma unroll
    for (int mf = 0; mf < 4; ++mf)
        #pragma unroll
        for (int nf = 0; nf < 4; ++nf)
            #pragma unroll
            for (int r = 0; r < 4; ++r) acc[mf][nf][r] = 0.f;

    auto load_stage = [&](int s, int chunk) {
        uint32_t abase = sb + s * STAGE_BYTES;
        uint32_t bbase = abase + A_BYTES;
        const char* asrc = asrc0 + chunk * (BK * 2);
        const char* bsrc = bsrc0 + chunk * (BK * 2);
        #pragma unroll
        for (int j = 0; j < 8; ++j) {
            int t = tid + j * 256;
            if (t < 1024) {
                int row = t >> 3, seg = t & 7;
                cp16(abase + SW128(row * 128 + seg * 16),
                     asrc + (size_t)row * (K_DIM * 2) + seg * 16);
            } else {
                int u = t - 1024;
                int row = u >> 3, seg = u & 7;
                cp16(bbase + SW128(row * 128 + seg * 16),
                     bsrc + (size_t)row * (K_DIM * 2) + seg * 16);
            }
        }
    };

    load_stage(0, 0);
    CP_COMMIT();
    load_stage(1, 1);
    CP_COMMIT();

    const int arow0 = wm * 64 + lrow;          // + mf*16
    const int brow0 = wn * 32 + lrow;          // + nf2*16

    #pragma unroll 1
    for (int i = 0; i < CHUNKS; ++i) {
        CP_WAIT(1);
        __syncthreads();

        if (i + 2 < CHUNKS)
            load_stage((i + 2) % STAGES, i + 2);
        CP_COMMIT();

        uint32_t abase = sb + (i % STAGES) * STAGE_BYTES;
        uint32_t bbase = abase + A_BYTES;

        #pragma unroll
        for (int ks = 0; ks < 4; ++ks) {
            uint32_t a[4][4], b[2][4];
            #pragma unroll
            for (int mf = 0; mf < 4; ++mf)
                LDSM4(a[mf], abase + SW128((arow0 + mf * 16) * 128 + ks * 32 + lhi));
            #pragma unroll
            for (int nf2 = 0; nf2 < 2; ++nf2)
                LDSM4(b[nf2], bbase + SW128((brow0 + nf2 * 16) * 128 + ks * 32 + lhi));
            #pragma unroll
            for (int mf = 0; mf < 4; ++mf)
                #pragma unroll
                for (int nf2 = 0; nf2 < 2; ++nf2) {
                    MMAB(acc[mf][2 * nf2],     a[mf], b[nf2][0], b[nf2][2]);
                    MMAB(acc[mf][2 * nf2 + 1], a[mf], b[nf2][1], b[nf2][3]);
                }
        }
    }

    // ---- epilogue: scale by gamma * eta/127, write float2 ----
    const float gamma = g_gamma;
    const int row0 = by * BM + wm * 64;
    const int col0 = bx * BN + wn * 32;
    const int rq = lane >> 2;
    const int cq = (lane & 3) * 2;
    #pragma unroll
    for (int mf = 0; mf < 4; ++mf) {
        int r = row0 + mf * 16 + rq;
        float s0 = gamma * g_eta[r];
        float s1 = gamma * g_eta[r + 8];
        float* p0 = out + (size_t)r * N_OUT + col0 + cq;
        float* p1 = out + (size_t)(r + 8) * N_OUT + col0 + cq;
        #pragma unroll
        for (int nf = 0; nf < 4; ++nf) {
            float2 o0 = make_float2(acc[mf][nf][0] * s0, acc[mf][nf][1] * s0);
            float2 o1 = make_float2(acc[mf][nf][2] * s1, acc[mf][nf][3] * s1);
            *(float2*)(p0 + nf * 8) = o0;
            *(float2*)(p1 + nf * 8) = o1;
        }
    }
}

// ======================= launch (3 kernels) =======================
extern "C" void kernel_launch(void* const* d_in, const int* in_sizes, int n_in,
                              void* d_out, int out_size) {
    const float* x = (const float*)d_in[0];
    const float* w = (const float*)d_in[1];
    float* out = (float*)d_out;

    cudaFuncSetAttribute(gemm_hmma, cudaFuncAttributeMaxDynamicSharedMemorySize, SMEM_TOTAL);

    ln_quant_x<<<M_TOK, 256>>>(x, w);    // LN + x-quant + |w| partials (x streamed)
    quant_w<<<2048, 256>>>(w);           // gamma reduce (folded) + w-quant (L2-hot w)
    gemm_hmma<<<dim3(N_OUT / BN, M_TOK / BM), 256, SMEM_TOTAL>>>(out);
}

// round 15
// speedup vs baseline: 1.0208x; 1.0085x over previous
#include <cuda_runtime.h>
#include <cuda_bf16.h>
#include <cstdint>

// Shapes: x (4,2048,2048) -> M=8192, K=2048; weight (8192,2048) -> N=8192.
#define M_TOK 8192
#define K_DIM 2048
#define N_OUT 8192
#define W_ELEMS (N_OUT * K_DIM)
#define X_ELEMS (M_TOK * K_DIM)

// GEMM tiling (bf16: BK=64 elems = 128 bytes per SMEM row)
#define BM 128
#define BN 128
#define BK 64
#define CHUNKS (K_DIM / BK)          // 32
#define STAGES 3
#define A_BYTES (BM * 128)           // 16384
#define B_BYTES (BN * 128)           // 16384
#define STAGE_BYTES (A_BYTES + B_BYTES)   // 32768
#define SMEM_TOTAL (1024 + STAGES * STAGE_BYTES)   // 99328 -> 2 CTAs/SM

// ---- device scratch ----
__device__ float g_gamma;
__device__ float g_partial[4096];         // one |w| partial per LN block (2 w-rows each)
__device__ float g_eta[M_TOK];            // eta/127 per token
__device__ __nv_bfloat16 g_xb[X_ELEMS];
__device__ __nv_bfloat16 g_wb[W_ELEMS];

// ======================= helpers =======================
__device__ __forceinline__ uint32_t smem_u32(const void* p) {
    uint32_t a;
    asm("{ .reg .u64 t; cvta.to.shared.u64 t, %1; cvt.u32.u64 %0, t; }" : "=r"(a) : "l"(p));
    return a;
}
#define SW128(o) ((o) ^ (((o) >> 3) & 0x70))

__device__ __forceinline__ void cp16(uint32_t dst, const void* src) {
    asm volatile("cp.async.cg.shared.global [%0], [%1], 16;" :: "r"(dst), "l"(src));
}
#define CP_COMMIT() asm volatile("cp.async.commit_group;" ::: "memory")
#define CP_WAIT(n)  asm volatile("cp.async.wait_group %0;" :: "n"(n) : "memory")

#define LDSM4(r, a)                                                                  \
    asm volatile("ldmatrix.sync.aligned.m8n8.x4.shared.b16 {%0,%1,%2,%3}, [%4];"     \
        : "=r"((r)[0]), "=r"((r)[1]), "=r"((r)[2]), "=r"((r)[3]) : "r"(a))

#define MMAB(d, a, b0, b1)                                                           \
    asm volatile("mma.sync.aligned.m16n8k16.row.col.f32.bf16.bf16.f32 "              \
        "{%0,%1,%2,%3}, {%4,%5,%6,%7}, {%8,%9}, {%0,%1,%2,%3};"                      \
        : "+f"((d)[0]), "+f"((d)[1]), "+f"((d)[2]), "+f"((d)[3])                     \
        : "r"((a)[0]), "r"((a)[1]), "r"((a)[2]), "r"((a)[3]), "r"(b0), "r"(b1))

// ======================= prepass 1: LN + x-quant (2 rows) + |w| partial =======================
// Block b: LayerNorm+quant of token rows 2b, 2b+1 (x streamed, MLP=4),
// AND abs-sum of w rows 2b, 2b+1 (kept L2-resident for quant_w).
__global__ void ln_quant_x(const float* __restrict__ x, const float* __restrict__ w) {
    int row0 = blockIdx.x * 2;
    int tid = threadIdx.x;
    const float4* xr0 = (const float4*)(x + (size_t)row0 * K_DIM);
    const float4* xr1 = (const float4*)(x + (size_t)(row0 + 1) * K_DIM);
    const float4* wr  = (const float4*)w + (size_t)row0 * 512;

    float4 a0 = __ldcs(xr0 + tid);
    float4 a1 = __ldcs(xr0 + tid + 256);
    float4 b0 = __ldcs(xr1 + tid);
    float4 b1 = __ldcs(xr1 + tid + 256);
    float4 w0 = wr[tid];
    float4 w1 = wr[tid + 256];
    float4 w2 = wr[tid + 512];
    float4 w3 = wr[tid + 768];
    float va[8] = {a0.x, a0.y, a0.z, a0.w, a1.x, a1.y, a1.z, a1.w};
    float vb[8] = {b0.x, b0.y, b0.z, b0.w, b1.x, b1.y, b1.z, b1.w};

    float s0 = 0.f, ss0 = 0.f, s1 = 0.f, ss1 = 0.f;
    #pragma unroll
    for (int i = 0; i < 8; ++i) {
        s0 += va[i]; ss0 += va[i] * va[i];
        s1 += vb[i]; ss1 += vb[i] * vb[i];
    }
    float wsum = fabsf(w0.x) + fabsf(w0.y) + fabsf(w0.z) + fabsf(w0.w)
               + fabsf(w1.x) + fabsf(w1.y) + fabsf(w1.z) + fabsf(w1.w)
               + fabsf(w2.x) + fabsf(w2.y) + fabsf(w2.z) + fabsf(w2.w)
               + fabsf(w3.x) + fabsf(w3.y) + fabsf(w3.z) + fabsf(w3.w);

    __shared__ float sh0s[8], sh0q[8], sh1s[8], sh1q[8], shw[8], shm0[8], shm1[8];
    #pragma unroll
    for (int o = 16; o; o >>= 1) {
        s0   += __shfl_down_sync(0xFFFFFFFFu, s0, o);
        ss0  += __shfl_down_sync(0xFFFFFFFFu, ss0, o);
        s1   += __shfl_down_sync(0xFFFFFFFFu, s1, o);
        ss1  += __shfl_down_sync(0xFFFFFFFFu, ss1, o);
        wsum += __shfl_down_sync(0xFFFFFFFFu, wsum, o);
    }
    if ((tid & 31) == 0) {
        int wi = tid >> 5;
        sh0s[wi] = s0; sh0q[wi] = ss0; sh1s[wi] = s1; sh1q[wi] = ss1; shw[wi] = wsum;
    }
    __syncthreads();
    float t0s = 0.f, t0q = 0.f, t1s = 0.f, t1q = 0.f;
    #pragma unroll
    for (int i = 0; i < 8; ++i) {
        t0s += sh0s[i]; t0q += sh0q[i]; t1s += sh1s[i]; t1q += sh1q[i];
    }
    if (tid == 0) {
        float wt = 0.f;
        #pragma unroll
        for (int i = 0; i < 8; ++i) wt += shw[i];
        g_partial[blockIdx.x] = wt;
    }

    float mean0 = t0s * (1.0f / K_DIM);
    float var0  = fmaxf(t0q * (1.0f / K_DIM) - mean0 * mean0, 0.0f);
    float rstd0 = rsqrtf(var0 + 1e-5f);
    float mean1 = t1s * (1.0f / K_DIM);
    float var1  = fmaxf(t1q * (1.0f / K_DIM) - mean1 * mean1, 0.0f);
    float rstd1 = rsqrtf(var1 + 1e-5f);

    float mx0 = 0.f, mx1 = 0.f;
    #pragma unroll
    for (int i = 0; i < 8; ++i) {
        va[i] = (va[i] - mean0) * rstd0;
        vb[i] = (vb[i] - mean1) * rstd1;
        mx0 = fmaxf(mx0, fabsf(va[i]));
        mx1 = fmaxf(mx1, fabsf(vb[i]));
    }
    #pragma unroll
    for (int o = 16; o; o >>= 1) {
        mx0 = fmaxf(mx0, __shfl_down_sync(0xFFFFFFFFu, mx0, o));
        mx1 = fmaxf(mx1, __shfl_down_sync(0xFFFFFFFFu, mx1, o));
    }
    if ((tid & 31) == 0) { shm0[tid >> 5] = mx0; shm1[tid >> 5] = mx1; }
    __syncthreads();
    float eta0 = 1e-5f, eta1 = 1e-5f;
    #pragma unroll
    for (int i = 0; i < 8; ++i) {
        eta0 = fmaxf(eta0, shm0[i]);
        eta1 = fmaxf(eta1, shm1[i]);
    }

    float q0 = 127.0f / eta0, q1 = 127.0f / eta1;
    float ba[8], bb[8];
    #pragma unroll
    for (int i = 0; i < 8; ++i) {
        ba[i] = rintf(fminf(fmaxf(va[i] * q0, -128.f), 127.f));
        bb[i] = rintf(fminf(fmaxf(vb[i] * q1, -128.f), 127.f));
    }

    __nv_bfloat162 pa0 = __floats2bfloat162_rn(ba[0], ba[1]);
    __nv_bfloat162 pa1 = __floats2bfloat162_rn(ba[2], ba[3]);
    __nv_bfloat162 pa2 = __floats2bfloat162_rn(ba[4], ba[5]);
    __nv_bfloat162 pa3 = __floats2bfloat162_rn(ba[6], ba[7]);
    __nv_bfloat162 pb0 = __floats2bfloat162_rn(bb[0], bb[1]);
    __nv_bfloat162 pb1 = __floats2bfloat162_rn(bb[2], bb[3]);
    __nv_bfloat162 pb2 = __floats2bfloat162_rn(bb[4], bb[5]);
    __nv_bfloat162 pb3 = __floats2bfloat162_rn(bb[6], bb[7]);
    uint2* xq0 = (uint2*)(g_xb + (size_t)row0 * K_DIM);
    uint2* xq1 = (uint2*)(g_xb + (size_t)(row0 + 1) * K_DIM);
    xq0[tid]       = make_uint2(*(uint32_t*)&pa0, *(uint32_t*)&pa1);
    xq0[tid + 256] = make_uint2(*(uint32_t*)&pa2, *(uint32_t*)&pa3);
    xq1[tid]       = make_uint2(*(uint32_t*)&pb0, *(uint32_t*)&pb1);
    xq1[tid + 256] = make_uint2(*(uint32_t*)&pb2, *(uint32_t*)&pb3);

    if (tid == 0) {
        g_eta[row0]     = eta0 * (1.0f / 127.0f);
        g_eta[row0 + 1] = eta1 * (1.0f / 127.0f);
    }
}

// ======================= prepass 2: gamma reduce (folded) + w-quant =======================
// Every block (256 threads) deterministically reduces the 4096 partials to the
// SAME gamma, then grid-strides the ternary quantization (w streamed: dead after
// this kernel; preserves g_xb/g_wb in L2 for the GEMM).
__global__ void quant_w(const float* __restrict__ w) {
    __shared__ float sh[8];
    __shared__ float sh_gamma;
    {
        float s = 0.f;
        #pragma unroll
        for (int j = 0; j < 16; ++j) s += g_partial[threadIdx.x + j * 256];
        #pragma unroll
        for (int o = 16; o; o >>= 1) s += __shfl_down_sync(0xFFFFFFFFu, s, o);
        if ((threadIdx.x & 31) == 0) sh[threadIdx.x >> 5] = s;
    }
    __syncthreads();
    if (threadIdx.x == 0) {
        float t = 0.f;
        #pragma unroll
        for (int i = 0; i < 8; ++i) t += sh[i];
        float gm = fmaxf(t / (float)W_ELEMS, 1e-5f);
        sh_gamma = gm;
        if (blockIdx.x == 0) g_gamma = gm;
    }
    __syncthreads();
    float inv_g = 1.0f / sh_gamma;

    const float4* w4 = (const float4*)w;
    uint2* out = (uint2*)g_wb;
    int stride = gridDim.x * blockDim.x;
    for (int i = blockIdx.x * blockDim.x + threadIdx.x; i < W_ELEMS / 4; i += stride) {
        float4 v = __ldcs(w4 + i);          // w dead after this kernel: stream it
        float b0 = rintf(fminf(fmaxf(v.x * inv_g, -1.f), 1.f));
        float b1 = rintf(fminf(fmaxf(v.y * inv_g, -1.f), 1.f));
        float b2 = rintf(fminf(fmaxf(v.z * inv_g, -1.f), 1.f));
        float b3 = rintf(fminf(fmaxf(v.w * inv_g, -1.f), 1.f));
        __nv_bfloat162 p0 = __floats2bfloat162_rn(b0, b1);
        __nv_bfloat162 p1 = __floats2bfloat162_rn(b2, b3);
        out[i] = make_uint2(*(uint32_t*)&p0, *(uint32_t*)&p1);
    }
}

// ======================= bf16 tensor-core GEMM (frozen R9/R12 config) =======================
// 256 threads = 8 warps in 2(m) x 4(n); warp tile 64x32; 2 CTAs per SM.
__global__ void __launch_bounds__(256, 2) gemm_hmma(float* __restrict__ out) {
    extern __shared__ char smem[];
    uint32_t sb = (smem_u32(smem) + 1023u) & ~1023u;

    const int tid  = threadIdx.x;
    const int lane = tid & 31;
    const int wid  = tid >> 5;
    const int wm   = wid >> 2;        // 0..1 (64 rows each)
    const int wn   = wid & 3;         // 0..3 (32 cols each)
    const int bx   = blockIdx.x;
    const int by   = blockIdx.y;

    const char* asrc0 = (const char*)(g_xb + (size_t)(by * BM) * K_DIM);
    const char* bsrc0 = (const char*)(g_wb + (size_t)(bx * BN) * K_DIM);

    const int lrow = lane & 15;
    const int lhi  = (lane & 16);

    float acc[4][4][4];
    #pragma unroll
    for (int mf = 0; mf < 4; ++mf)
        #pragma unroll
        for (int nf = 0; nf < 4; ++nf)
            #pragma unroll
            for (int r = 0; r < 4; ++r) acc[mf][nf][r] = 0.f;

    auto load_stage = [&](int s, int chunk) {
        uint32_t abase = sb + s * STAGE_BYTES;
        uint32_t bbase = abase + A_BYTES;
        const char* asrc = asrc0 + chunk * (BK * 2);
        const char* bsrc = bsrc0 + chunk * (BK * 2);
        #pragma unroll
        for (int j = 0; j < 8; ++j) {
            int t = tid + j * 256;
            if (t < 1024) {
                int row = t >> 3, seg = t & 7;
                cp16(abase + SW128(row * 128 + seg * 16),
                     asrc + (size_t)row * (K_DIM * 2) + seg * 16);
            } else {
                int u = t - 1024;
                int row = u >> 3, seg = u & 7;
                cp16(bbase + SW128(row * 128 + seg * 16),
                     bsrc + (size_t)row * (K_DIM * 2) + seg * 16);
            }
        }
    };

    load_stage(0, 0);
    CP_COMMIT();
    load_stage(1, 1);
    CP_COMMIT();

    const int arow0 = wm * 64 + lrow;          // + mf*16
    const int brow0 = wn * 32 + lrow;          // + nf2*16

    #pragma unroll 1
    for (int i = 0; i < CHUNKS; ++i) {
        CP_WAIT(1);
        __syncthreads();

        if (i + 2 < CHUNKS)
            load_stage((i + 2) % STAGES, i + 2);
        CP_COMMIT();

        uint32_t abase = sb + (i % STAGES) * STAGE_BYTES;
        uint32_t bbase = abase + A_BYTES;

        #pragma unroll
        for (int ks = 0; ks < 4; ++ks) {
            uint32_t a[4][4], b[2][4];
            #pragma unroll
            for (int mf = 0; mf < 4; ++mf)
                LDSM4(a[mf], abase + SW128((arow0 + mf * 16) * 128 + ks * 32 + lhi));
            #pragma unroll
            for (int nf2 = 0; nf2 < 2; ++nf2)
                LDSM4(b[nf2], bbase + SW128((brow0 + nf2 * 16) * 128 + ks * 32 + lhi));
            #pragma unroll
            for (int mf = 0; mf < 4; ++mf)
                #pragma unroll
                for (int nf2 = 0; nf2 < 2; ++nf2) {
                    MMAB(acc[mf][2 * nf2],     a[mf], b[nf2][0], b[nf2][2]);
                    MMAB(acc[mf][2 * nf2 + 1], a[mf], b[nf2][1], b[nf2][3]);
                }
        }
    }

    // ---- epilogue: scale by gamma * eta/127, write float2 ----
    const float gamma = g_gamma;
    const int row0 = by * BM + wm * 64;
    const int col0 = bx * BN + wn * 32;
    const int rq = lane >> 2;
    const int cq = (lane & 3) * 2;
    #pragma unroll
    for (int mf = 0; mf < 4; ++mf) {
        int r = row0 + mf * 16 + rq;
        float s0 = gamma * g_eta[r];
        float s1 = gamma * g_eta[r + 8];
        float* p0 = out + (size_t)r * N_OUT + col0 + cq;
        float* p1 = out + (size_t)(r + 8) * N_OUT + col0 + cq;
        #pragma unroll
        for (int nf = 0; nf < 4; ++nf) {
            float2 o0 = make_float2(acc[mf][nf][0] * s0, acc[mf][nf][1] * s0);
            float2 o1 = make_float2(acc[mf][nf][2] * s1, acc[mf][nf][3] * s1);
            *(float2*)(p0 + nf * 8) = o0;
            *(float2*)(p1 + nf * 8) = o1;
        }
    }
}

// ======================= launch (3 kernels) =======================
extern "C" void kernel_launch(void* const* d_in, const int* in_sizes, int n_in,
                              void* d_out, int out_size) {
    const float* x = (const float*)d_in[0];
    const float* w = (const float*)d_in[1];
    float* out = (float*)d_out;

    cudaFuncSetAttribute(gemm_hmma, cudaFuncAttributeMaxDynamicSharedMemorySize, SMEM_TOTAL);

    ln_quant_x<<<M_TOK / 2, 256>>>(x, w);   // LN + x-quant (2 rows) + |w| partials
    quant_w<<<2048, 256>>>(w);              // gamma reduce (folded) + w-quant (streamed)
    gemm_hmma<<<dim3(N_OUT / BN, M_TOK / BM), 256, SMEM_TOTAL>>>(out);
}